// round 13
// baseline (speedup 1.0000x reference)
#include <cuda_runtime.h>
#include <cuda_bf16.h>

// x:    [B=64, C=64, S=8192] float32
// mask: [B=64, S=8192] int32
// out:  patches [64, 512, 1024] float32  followed by  padding_mask [64, 512] float32
//
// patches[b, p, c*16 + j] = x[b, c, p*16 + j]   (stride == patch -> pure permutation)
// padding_mask[b, p] = (sum(mask[b, p*16 : p*16+16]) >= 8) ? 1.0f : 0.0f
//
// Best-known config (R9/R10: ~35.4us kernel = 7.65 TB/s combined ≈ 96% of HBM
// spec; mask blocks first so their latency hides under the streaming permute).
// R11: 256-bit loads/stores (sm_103a ld/st.global.v8.f32). An even-aligned
// pair of consecutive output float4s is 32B-contiguous and 32B-aligned in BOTH
// source and dest, so each thread does 2x LDG.256 + 2x STG.256 instead of
// 4x128-bit each way: same bytes and coalescing, half the L1tex wavefronts.

#define B       64
#define C       64
#define S       8192
#define NP      512                       // n_patches
#define CP      1024                      // C * PATCH
#define TOTAL_OUT_F4     (B * NP * CP / 4)       // 8388608
#define F4_PER_BLOCK     1024                    // 256 threads x 2 pairs x 2 f4
#define PERMUTE_BLOCKS   (TOTAL_OUT_F4 / F4_PER_BLOCK)  // 8192
#define MASK_THREADS     (B * NP)                // 32768
#define MASK_BLOCKS      ((MASK_THREADS + 255) / 256)   // 128

__device__ __forceinline__ void ldg256(const float4* p, float4& a, float4& b) {
    asm volatile("ld.global.v8.f32 {%0,%1,%2,%3,%4,%5,%6,%7}, [%8];"
                 : "=f"(a.x), "=f"(a.y), "=f"(a.z), "=f"(a.w),
                   "=f"(b.x), "=f"(b.y), "=f"(b.z), "=f"(b.w)
                 : "l"(p));
}

__device__ __forceinline__ void stg256(float4* p, const float4& a, const float4& b) {
    asm volatile("st.global.v8.f32 [%0], {%1,%2,%3,%4,%5,%6,%7,%8};"
                 :: "l"(p),
                    "f"(a.x), "f"(a.y), "f"(a.z), "f"(a.w),
                    "f"(b.x), "f"(b.y), "f"(b.z), "f"(b.w)
                 : "memory");
}

__device__ __forceinline__ int src_of_pair(int f4idx) {
    // f4idx is even; source pair is contiguous (j4, j4+1) within a 64B run.
    int b  = f4idx >> 17;                 // / 131072 (f4 per batch)
    int r  = f4idx & ((NP * CP / 4) - 1);
    int p  = r >> 8;                      // / 256
    int r2 = r & 255;
    int c  = r2 >> 2;                     // / 4
    int j4 = r2 & 3;                      // even
    return ((b << 6) + c) * (S / 4) + (p << 2) + j4;
}

__global__ void __launch_bounds__(256)
fused_patch_kernel(const float4* __restrict__ x4,
                   const int4* __restrict__ m4,
                   float4* __restrict__ out4,
                   float* __restrict__ pm) {
    int blk = blockIdx.x;
    if (blk >= MASK_BLOCKS) {
        // ---- permute: 2 independent LDG.256 then 2 STG.256 ----
        // pair q covers output f4 {2q, 2q+1}; thread handles q0 and q0+256.
        int q0 = (blk - MASK_BLOCKS) * (F4_PER_BLOCK / 2) + threadIdx.x;
        int d0 = 2 * q0;                          // even f4 index, 32B aligned
        int d1 = 2 * (q0 + 256);
        float4 a0, b0, a1, b1;
        ldg256(&x4[src_of_pair(d0)], a0, b0);
        ldg256(&x4[src_of_pair(d1)], a1, b1);
        stg256(&out4[d0], a0, b0);
        stg256(&out4[d1], a1, b1);
    } else {
        // ---- mask: one (b,p) per thread; scheduled first, hides under permute ----
        int t = blk * 256 + threadIdx.x;
        int b = t >> 9;                           // / 512
        int p = t & (NP - 1);
        int mbase = (b * S + p * 16) >> 2;
        int s = 0;
        #pragma unroll
        for (int k = 0; k < 4; k++) {
            int4 m = m4[mbase + k];
            s += m.x + m.y + m.z + m.w;
        }
        pm[t] = (s >= 8) ? 1.0f : 0.0f;
    }
}

extern "C" void kernel_launch(void* const* d_in, const int* in_sizes, int n_in,
                              void* d_out, int out_size) {
    const float4* x4 = (const float4*)d_in[0];
    const int4*   m4 = (const int4*)d_in[1];
    float* out = (float*)d_out;
    float* pm  = out + (size_t)B * NP * CP;

    fused_patch_kernel<<<MASK_BLOCKS + PERMUTE_BLOCKS, 256>>>(
        x4, m4, (float4*)out, pm);
}